// round 16
// baseline (speedup 1.0000x reference)
#include <cuda_runtime.h>
#include <cuda_fp16.h>
#include <math.h>
#include <stdint.h>

#define NB 2
#define NT 2048
#define NC 1024
#define NH 16
#define ND 64
#define MTOT (NB*NT)   // 4096

// Scratch (device globals) — fp16
__device__ __half g_q[NB*NH*NT*ND];
__device__ __half g_k[NB*NH*NT*ND];
__device__ __half g_v[NB*NH*NT*ND];
__device__ __half g_y[NB*NT*NC];
__device__ __half g_x[MTOT*NC];
__device__ __half g_wq[NC*NC];
__device__ __half g_wk[NC*NC];
__device__ __half g_wv[NC*NC];
__device__ __half g_wp[NC*NC];

__device__ __forceinline__ unsigned smem_u32(const void* p) {
    unsigned r;
    asm("{ .reg .u64 t; cvta.to.shared.u64 t, %1; cvt.u32.u64 %0, t; }"
        : "=r"(r) : "l"(p));
    return r;
}

__device__ __forceinline__ void ldsm4(unsigned& r0, unsigned& r1,
                                      unsigned& r2, unsigned& r3, unsigned addr)
{
    asm volatile("ldmatrix.sync.aligned.m8n8.x4.shared.b16 {%0,%1,%2,%3}, [%4];"
                 : "=r"(r0), "=r"(r1), "=r"(r2), "=r"(r3) : "r"(addr));
}
__device__ __forceinline__ void ldsm4t(unsigned& r0, unsigned& r1,
                                       unsigned& r2, unsigned& r3, unsigned addr)
{
    asm volatile("ldmatrix.sync.aligned.m8n8.x4.trans.shared.b16 {%0,%1,%2,%3}, [%4];"
                 : "=r"(r0), "=r"(r1), "=r"(r2), "=r"(r3) : "r"(addr));
}

// fp16 MMA, fp32 accumulate: D(16x8) += A(16x16) * B(16x8)
__device__ __forceinline__ void mma_f16(float c[4], unsigned a0, unsigned a1,
                                        unsigned a2, unsigned a3,
                                        unsigned b0, unsigned b1)
{
    asm volatile(
        "mma.sync.aligned.m16n8k16.row.col.f32.f16.f16.f32 "
        "{%0,%1,%2,%3}, {%4,%5,%6,%7}, {%8,%9}, {%0,%1,%2,%3};"
        : "+f"(c[0]), "+f"(c[1]), "+f"(c[2]), "+f"(c[3])
        : "r"(a0), "r"(a1), "r"(a2), "r"(a3), "r"(b0), "r"(b1));
}

__device__ __forceinline__ void cpa16(unsigned dst, const void* src) {
    asm volatile("cp.async.cg.shared.global [%0], [%1], 16;" :: "r"(dst), "l"(src));
}
__device__ __forceinline__ void cp_commit() {
    asm volatile("cp.async.commit_group;");
}
template<int N> __device__ __forceinline__ void cp_wait() {
    asm volatile("cp.async.wait_group %0;" :: "n"(N));
}

// ---------------------------------------------------------------------------
// Prep (single launch): round x and 4 weight matrices to fp16.
// ---------------------------------------------------------------------------
#define X4   (MTOT*NC/4)
#define W4   (NC*NC/4)
#define TOT4 (X4 + 4*W4)

__global__ __launch_bounds__(256)
void prep_f16(const float4* __restrict__ x,  const float4* __restrict__ wq,
              const float4* __restrict__ wk, const float4* __restrict__ wv,
              const float4* __restrict__ wp)
{
    const int i = blockIdx.x * 256 + threadIdx.x;
    if (i >= TOT4) return;
    const float4* s; __half* d; int off;
    if (i < X4) { s = x; d = g_x; off = i; }
    else {
        const int j = i - X4;
        const int w = j >> 18;
        off = j & (W4 - 1);
        switch (w) {
            case 0:  s = wq; d = g_wq; break;
            case 1:  s = wk; d = g_wk; break;
            case 2:  s = wv; d = g_wv; break;
            default: s = wp; d = g_wp; break;
        }
    }
    float4 v = s[off];
    __half2 h01 = __floats2half2_rn(v.x, v.y);
    __half2 h23 = __floats2half2_rn(v.z, v.w);
    uint2 u;
    u.x = *(unsigned*)&h01;
    u.y = *(unsigned*)&h23;
    *(uint2*)(d + off * 4) = u;
}

// ---------------------------------------------------------------------------
// FP16 NT GEMM: block tile 128x128, warp tile 32x64 (8 warps, 4x2), BK=64,
// cp.async 2-stage (round-12 measured-best configuration, unchanged).
// ---------------------------------------------------------------------------
#define GBM 128
#define GBN 128
#define GBK 64
#define GPD 72                            // halves per row (144B pitch)
#define A_BYTES (GBM*GPD*2)               // 18432
#define B_BYTES (GBN*GPD*2)               // 18432
#define STG_BYTES (A_BYTES + B_BYTES)     // 36864
#define GEMM_SMEM_BYTES (2*STG_BYTES)     // 73728

__device__ __forceinline__ void gemm_tc(const __half* __restrict__ A,
                                        const __half* __restrict__ W,
                                        float C[2][8][4], int m0, int n0)
{
    extern __shared__ unsigned char smp[];
    const unsigned sbase = smem_u32(smp);

    const int tid  = threadIdx.x;
    const int wid  = tid >> 5;
    const int lane = tid & 31;
    const int wr   = wid >> 1;   // m offset wr*32
    const int wc   = wid & 1;    // n offset wc*64

    const int aRow = lane & 15;
    const int aCol = ((lane >> 4) & 1) << 3;
    const int bRow = (lane & 7) + (((lane >> 4) & 1) << 3);
    const int bCol = ((lane >> 3) & 1) << 3;

    auto stage = [&](unsigned soff, int k0) {
        #pragma unroll
        for (int i = 0; i < 4; i++) {
            const int c   = tid + i * 256;
            const int row = c >> 3;
            const int c8  = (c & 7) << 3;
            cpa16(sbase + soff + (unsigned)(row * GPD + c8) * 2,
                  A + (size_t)(m0 + row) * NC + k0 + c8);
        }
        #pragma unroll
        for (int i = 0; i < 4; i++) {
            const int c   = tid + i * 256;
            const int row = c >> 3;
            const int c8  = (c & 7) << 3;
            cpa16(sbase + soff + A_BYTES + (unsigned)(row * GPD + c8) * 2,
                  W + (size_t)(n0 + row) * NC + k0 + c8);
        }
    };

    stage(0, 0);
    cp_commit();

    const int NIT = NC / GBK;   // 16
    for (int it = 0; it < NIT; it++) {
        cp_wait<0>();
        __syncthreads();
        if (it + 1 < NIT) {
            stage((unsigned)((it + 1) & 1) * STG_BYTES, (it + 1) * GBK);
            cp_commit();
        }
        const unsigned cs = (unsigned)(it & 1) * STG_BYTES;
        const unsigned aBase = sbase + cs;
        const unsigned bBase = sbase + cs + A_BYTES;

        #pragma unroll
        for (int kk = 0; kk < GBK; kk += 16) {
            unsigned a[2][4], b[8][2];
            #pragma unroll
            for (int mt = 0; mt < 2; mt++)
                ldsm4(a[mt][0], a[mt][1], a[mt][2], a[mt][3],
                      aBase + (unsigned)((wr * 32 + mt * 16 + aRow) * GPD + kk + aCol) * 2);
            #pragma unroll
            for (int p = 0; p < 4; p++)
                ldsm4(b[2*p][0], b[2*p][1], b[2*p+1][0], b[2*p+1][1],
                      bBase + (unsigned)((wc * 64 + p * 16 + bRow) * GPD + kk + bCol) * 2);
            #pragma unroll
            for (int mt = 0; mt < 2; mt++)
                #pragma unroll
                for (int nt = 0; nt < 8; nt++)
                    mma_f16(C[mt][nt], a[mt][0], a[mt][1], a[mt][2], a[mt][3],
                            b[nt][0], b[nt][1]);
        }
    }
}

__global__ __launch_bounds__(256, 2)
void qkv_kernel(const float* __restrict__ bq, const float* __restrict__ bk,
                const float* __restrict__ bv)
{
    const __half* W; const float* bias; __half* Out;
    if (blockIdx.z == 0)      { W = g_wq; bias = bq; Out = g_q; }
    else if (blockIdx.z == 1) { W = g_wk; bias = bk; Out = g_k; }
    else                      { W = g_wv; bias = bv; Out = g_v; }

    const int m0 = blockIdx.y * GBM;
    const int n0 = blockIdx.x * GBN;
    float C[2][8][4] = {};
    gemm_tc(g_x, W, C, m0, n0);

    const int lane = threadIdx.x & 31, wid = threadIdx.x >> 5;
    const int g = lane >> 2, t = lane & 3;
    const int wr = wid >> 1, wc = wid & 1;

    #pragma unroll
    for (int mt = 0; mt < 2; mt++) {
        #pragma unroll
        for (int rr = 0; rr < 2; rr++) {
            const int m = m0 + wr * 32 + mt * 16 + g + rr * 8;
            const int b = m >> 11;
            const int tt = m & (NT - 1);
            #pragma unroll
            for (int nt = 0; nt < 8; nt++) {
                const int n  = n0 + wc * 64 + nt * 8 + 2 * t;
                const int h  = n >> 6;
                const int hd = n & 63;
                __half* op = Out + (((size_t)(b * NH + h)) * NT + tt) * ND + hd;
                __half2 hv = __floats2half2_rn(C[mt][nt][rr * 2 + 0] + bias[n],
                                               C[mt][nt][rr * 2 + 1] + bias[n + 1]);
                *(__half2*)op = hv;
            }
        }
    }
}

__global__ __launch_bounds__(256, 2)
void proj_kernel(const float* __restrict__ bp, float* __restrict__ out)
{
    const int m0 = blockIdx.y * GBM;
    const int n0 = blockIdx.x * GBN;
    float C[2][8][4] = {};
    gemm_tc(g_y, g_wp, C, m0, n0);

    const int lane = threadIdx.x & 31, wid = threadIdx.x >> 5;
    const int g = lane >> 2, t = lane & 3;
    const int wr = wid >> 1, wc = wid & 1;

    #pragma unroll
    for (int mt = 0; mt < 2; mt++) {
        #pragma unroll
        for (int rr = 0; rr < 2; rr++) {
            const int m = m0 + wr * 32 + mt * 16 + g + rr * 8;
            #pragma unroll
            for (int nt = 0; nt < 8; nt++) {
                const int n = n0 + wc * 64 + nt * 8 + 2 * t;
                float2 v;
                v.x = C[mt][nt][rr * 2 + 0] + bp[n];
                v.y = C[mt][nt][rr * 2 + 1] + bp[n + 1];
                *(float2*)(out + (size_t)m * NC + n) = v;
            }
        }
    }
}

// ---------------------------------------------------------------------------
// FP16 flash attention: 512 threads / 16 warps / 256 q-rows per block.
// Per-warp code identical to round 12 (16 rows/warp, register-P, __expf
// softmax, 2-stage K/V cp.async staging). One staging+sync train now serves
// 256 q-rows -> 47% less staging/barrier work, same MMA work.
// ---------------------------------------------------------------------------
#define ATHR 512
#define AQT  256                        // q-rows per block
#define APDH 72
#define KVB (64*APDH*2)                 // 9216 B per buffer
#define ATT_SMEM_BYTES (4*KVB)          // K0 K1 V0 V1 = 36864

__global__ __launch_bounds__(ATHR)
void attn_kernel()
{
    extern __shared__ unsigned char sma[];
    const unsigned sbase = smem_u32(sma);

    const int tid  = threadIdx.x;
    const int wid  = tid >> 5;          // 0..15
    const int lane = tid & 31;
    const int g    = lane >> 2;
    const int t    = lane & 3;

    const int bh = blockIdx.y;
    const int qb = gridDim.x - 1 - blockIdx.x;   // heavy blocks first
    const int q0 = qb * AQT;
    const int rb = wid * 16;                     // warp row base within block
    const int qr_max = q0 + rb + 15;

    const int bRow = (lane & 7) + (((lane >> 4) & 1) << 3);
    const int bCol = ((lane >> 3) & 1) << 3;
    const int vRow = lane & 15;
    const int vCol = ((lane >> 4) & 1) << 3;

    // ---- Q fragments from gmem (x0.125 exact in fp16) ----
    unsigned Qf[4][4];
    {
        const __half* qp = g_q + ((size_t)bh * NT + q0 + rb) * ND;
        const __half2 s2 = __floats2half2_rn(0.125f, 0.125f);
        #pragma unroll
        for (int kt = 0; kt < 4; kt++) {
            __half2 v;
            v = __hmul2(*(const __half2*)(qp + (g)     * ND + kt * 16 + 2 * t), s2);
            Qf[kt][0] = *(unsigned*)&v;
            v = __hmul2(*(const __half2*)(qp + (g + 8) * ND + kt * 16 + 2 * t), s2);
            Qf[kt][1] = *(unsigned*)&v;
            v = __hmul2(*(const __half2*)(qp + (g)     * ND + kt * 16 + 2 * t + 8), s2);
            Qf[kt][2] = *(unsigned*)&v;
            v = __hmul2(*(const __half2*)(qp + (g + 8) * ND + kt * 16 + 2 * t + 8), s2);
            Qf[kt][3] = *(unsigned*)&v;
        }
    }

    float Of[8][4];
    #pragma unroll
    for (int nt = 0; nt < 8; nt++)
        #pragma unroll
        for (int j = 0; j < 4; j++) Of[nt][j] = 0.f;
    float mrow[2] = {-1e30f, -1e30f};
    float lrow[2] = {0.f, 0.f};

    const __half* kbase = g_k + (size_t)bh * NT * ND;
    const __half* vbase = g_v + (size_t)bh * NT * ND;

    const int ntiles = 4 * qb + 4;               // key tiles of 64 covering q0+255

    auto stage_tile = [&](int tile, int buf) {
        const unsigned kDst = sbase + (unsigned)buf * KVB;
        const unsigned vDst = sbase + (unsigned)(2 + buf) * KVB;
        // 512 chunks per array, 512 threads -> 1 chunk each
        const int row = tid >> 3;
        const int c8  = (tid & 7) << 3;
        const unsigned o = (unsigned)(row * APDH + c8) * 2;
        cpa16(kDst + o, kbase + (size_t)(tile * 64 + row) * ND + c8);
        cpa16(vDst + o, vbase + (size_t)(tile * 64 + row) * ND + c8);
    };

    stage_tile(0, 0);
    cp_commit();

    for (int kt0 = 0; kt0 < ntiles; kt0++) {
        const int cur = kt0 & 1;
        cp_wait<0>();
        __syncthreads();
        if (kt0 + 1 < ntiles) {
            stage_tile(kt0 + 1, cur ^ 1);
            cp_commit();
        }
        const unsigned kBuf = sbase + (unsigned)cur * KVB;
        const unsigned vBuf = sbase + (unsigned)(2 + cur) * KVB;

        const bool active = (kt0 * 64) <= qr_max;
        if (active) {
            // ---- S = Q K^T ----
            float Sf[8][4];
            #pragma unroll
            for (int nt = 0; nt < 8; nt++)
                #pragma unroll
                for (int j = 0; j < 4; j++) Sf[nt][j] = 0.f;

            #pragma unroll
            for (int kt = 0; kt < 4; kt++) {
                unsigned b[8][2];
                #pragma unroll
                for (int p = 0; p < 4; p++)
                    ldsm4(b[2*p][0], b[2*p][1], b[2*p+1][0], b[2*p+1][1],
                          kBuf + (unsigned)((p * 16 + bRow) * APDH + kt * 16 + bCol) * 2);
                #pragma unroll
                for (int nt = 0; nt < 8; nt++)
                    mma_f16(Sf[nt], Qf[kt][0], Qf[kt][1], Qf[kt][2], Qf[kt][3],
                            b[nt][0], b[nt][1]);
            }

            // ---- causal mask (diagonal region: keybase >= q0) ----
            if (kt0 >= 4 * qb) {
                #pragma unroll
                for (int nt = 0; nt < 8; nt++)
                    #pragma unroll
                    for (int j = 0; j < 4; j++) {
                        const int key = kt0 * 64 + nt * 8 + 2 * t + (j & 1);
                        const int qr  = q0 + rb + g + (j >> 1) * 8;
                        if (key > qr) Sf[nt][j] = -1e30f;
                    }
            }

            // ---- online softmax (round-12 form) ----
            #pragma unroll
            for (int r = 0; r < 2; r++) {
                float rm = -1e30f;
                #pragma unroll
                for (int nt = 0; nt < 8; nt++) {
                    rm = fmaxf(rm, Sf[nt][2 * r]);
                    rm = fmaxf(rm, Sf[nt][2 * r + 1]);
                }
                rm = fmaxf(rm, __shfl_xor_sync(0xffffffff, rm, 1));
                rm = fmaxf(rm, __shfl_xor_sync(0xffffffff, rm, 2));
                const float mn   = fmaxf(mrow[r], rm);
                const float corr = __expf(mrow[r] - mn);
                mrow[r] = mn;
                float rs = 0.f;
                #pragma unroll
                for (int nt = 0; nt < 8; nt++) {
                    const float p0 = __expf(Sf[nt][2 * r]     - mn);
                    const float p1 = __expf(Sf[nt][2 * r + 1] - mn);
                    Sf[nt][2 * r] = p0; Sf[nt][2 * r + 1] = p1;
                    rs += p0 + p1;
                }
                rs += __shfl_xor_sync(0xffffffff, rs, 1);
                rs += __shfl_xor_sync(0xffffffff, rs, 2);
                lrow[r] = lrow[r] * corr + rs;
                #pragma unroll
                for (int nt = 0; nt < 8; nt++) {
                    Of[nt][2 * r]     *= corr;
                    Of[nt][2 * r + 1] *= corr;
                }
            }

            // ---- O += P V : P packed straight from S fragments ----
            #pragma unroll
            for (int kt = 0; kt < 4; kt++) {
                __half2 p0 = __floats2half2_rn(Sf[2*kt][0],   Sf[2*kt][1]);
                __half2 p1 = __floats2half2_rn(Sf[2*kt][2],   Sf[2*kt][3]);
                __half2 p2 = __floats2half2_rn(Sf[2*kt+1][0], Sf[2*kt+1][1]);
                __half2 p3 = __floats2half2_rn(Sf[2*kt+1][2], Sf[2*kt+1][3]);
                const unsigned a0 = *(unsigned*)&p0;
                const unsigned a1 = *(unsigned*)&p1;
                const unsigned a2 = *(unsigned*)&p2;
                const unsigned a3 = *(unsigned*)&p3;
                unsigned b[8][2];
                #pragma unroll
                for (int p = 0; p < 4; p++)
                    ldsm4t(b[2*p][0], b[2*p][1], b[2*p+1][0], b[2*p+1][1],
                           vBuf + (unsigned)((kt * 16 + vRow) * APDH + p * 16 + vCol) * 2);
                #pragma unroll
                for (int nt = 0; nt < 8; nt++)
                    mma_f16(Of[nt], a0, a1, a2, a3, b[nt][0], b[nt][1]);
            }
        }
        __syncthreads();
    }

    // ---- epilogue: divide by l, store half for proj ----
    const float inv0 = 1.0f / lrow[0];
    const float inv1 = 1.0f / lrow[1];
    const int b = bh >> 4;
    const int h = bh & 15;
    __half* yp = g_y + ((size_t)(b * NT) + q0 + rb) * NC + h * ND;

    #pragma unroll
    for (int nt = 0; nt < 8; nt++) {
        const int c = nt * 8 + 2 * t;
        __half2 v0 = __floats2half2_rn(Of[nt][0] * inv0, Of[nt][1] * inv0);
        *(__half2*)(yp + (size_t)g * NC + c) = v0;
        __half2 v1 = __floats2half2_rn(Of[nt][2] * inv1, Of[nt][3] * inv1);
        *(__half2*)(yp + (size_t)(g + 8) * NC + c) = v1;
    }
}

// ---------------------------------------------------------------------------
extern "C" void kernel_launch(void* const* d_in, const int* in_sizes, int n_in,
                              void* d_out, int out_size)
{
    const float* x  = (const float*)d_in[0];
    const float* Wk = (const float*)d_in[1];
    const float* bk = (const float*)d_in[2];
    const float* Wq = (const float*)d_in[3];
    const float* bq = (const float*)d_in[4];
    const float* Wv = (const float*)d_in[5];
    const float* bv = (const float*)d_in[6];
    const float* Wp = (const float*)d_in[7];
    const float* bp = (const float*)d_in[8];
    float* out = (float*)d_out;

    static bool attr_done = false;
    if (!attr_done) {
        cudaFuncSetAttribute(qkv_kernel,
                             cudaFuncAttributeMaxDynamicSharedMemorySize, GEMM_SMEM_BYTES);
        cudaFuncSetAttribute(proj_kernel,
                             cudaFuncAttributeMaxDynamicSharedMemorySize, GEMM_SMEM_BYTES);
        cudaFuncSetAttribute(attn_kernel,
                             cudaFuncAttributeMaxDynamicSharedMemorySize, ATT_SMEM_BYTES);
        attr_done = true;
    }

    prep_f16<<<(TOT4 + 255) / 256, 256>>>((const float4*)x,  (const float4*)Wq,
                                          (const float4*)Wk, (const float4*)Wv,
                                          (const float4*)Wp);

    dim3 gq(NC / GBN, MTOT / GBM, 3);
    qkv_kernel<<<gq, 256, GEMM_SMEM_BYTES>>>(bq, bk, bv);

    dim3 ga(NT / AQT, NB * NH);
    attn_kernel<<<ga, ATHR, ATT_SMEM_BYTES>>>();

    dim3 gp(NC / GBN, MTOT / GBM);
    proj_kernel<<<gp, 256, GEMM_SMEM_BYTES>>>(bp, out);
}

// round 17
// speedup vs baseline: 1.0577x; 1.0577x over previous
#include <cuda_runtime.h>
#include <cuda_fp16.h>
#include <math.h>
#include <stdint.h>

#define NB 2
#define NT 2048
#define NC 1024
#define NH 16
#define ND 64
#define MTOT (NB*NT)   // 4096

// Scratch (device globals) — fp16
__device__ __half g_q[NB*NH*NT*ND];
__device__ __half g_k[NB*NH*NT*ND];
__device__ __half g_v[NB*NH*NT*ND];
__device__ __half g_y[NB*NT*NC];
__device__ __half g_x[MTOT*NC];
__device__ __half g_wq[NC*NC];
__device__ __half g_wk[NC*NC];
__device__ __half g_wv[NC*NC];
__device__ __half g_wp[NC*NC];

__device__ __forceinline__ unsigned smem_u32(const void* p) {
    unsigned r;
    asm("{ .reg .u64 t; cvta.to.shared.u64 t, %1; cvt.u32.u64 %0, t; }"
        : "=r"(r) : "l"(p));
    return r;
}

__device__ __forceinline__ void ldsm4(unsigned& r0, unsigned& r1,
                                      unsigned& r2, unsigned& r3, unsigned addr)
{
    asm volatile("ldmatrix.sync.aligned.m8n8.x4.shared.b16 {%0,%1,%2,%3}, [%4];"
                 : "=r"(r0), "=r"(r1), "=r"(r2), "=r"(r3) : "r"(addr));
}
__device__ __forceinline__ void ldsm4t(unsigned& r0, unsigned& r1,
                                       unsigned& r2, unsigned& r3, unsigned addr)
{
    asm volatile("ldmatrix.sync.aligned.m8n8.x4.trans.shared.b16 {%0,%1,%2,%3}, [%4];"
                 : "=r"(r0), "=r"(r1), "=r"(r2), "=r"(r3) : "r"(addr));
}

// fp16 MMA, fp32 accumulate: D(16x8) += A(16x16) * B(16x8)
__device__ __forceinline__ void mma_f16(float c[4], unsigned a0, unsigned a1,
                                        unsigned a2, unsigned a3,
                                        unsigned b0, unsigned b1)
{
    asm volatile(
        "mma.sync.aligned.m16n8k16.row.col.f32.f16.f16.f32 "
        "{%0,%1,%2,%3}, {%4,%5,%6,%7}, {%8,%9}, {%0,%1,%2,%3};"
        : "+f"(c[0]), "+f"(c[1]), "+f"(c[2]), "+f"(c[3])
        : "r"(a0), "r"(a1), "r"(a2), "r"(a3), "r"(b0), "r"(b1));
}

__device__ __forceinline__ void cpa16(unsigned dst, const void* src) {
    asm volatile("cp.async.cg.shared.global [%0], [%1], 16;" :: "r"(dst), "l"(src));
}
__device__ __forceinline__ void cp_commit() {
    asm volatile("cp.async.commit_group;");
}
template<int N> __device__ __forceinline__ void cp_wait() {
    asm volatile("cp.async.wait_group %0;" :: "n"(N));
}

// ---------------------------------------------------------------------------
// Prep (single launch): round x and 4 weight matrices to fp16.
// ---------------------------------------------------------------------------
#define X4   (MTOT*NC/4)
#define W4   (NC*NC/4)
#define TOT4 (X4 + 4*W4)

__global__ __launch_bounds__(256)
void prep_f16(const float4* __restrict__ x,  const float4* __restrict__ wq,
              const float4* __restrict__ wk, const float4* __restrict__ wv,
              const float4* __restrict__ wp)
{
    const int i = blockIdx.x * 256 + threadIdx.x;
    if (i >= TOT4) return;
    const float4* s; __half* d; int off;
    if (i < X4) { s = x; d = g_x; off = i; }
    else {
        const int j = i - X4;
        const int w = j >> 18;
        off = j & (W4 - 1);
        switch (w) {
            case 0:  s = wq; d = g_wq; break;
            case 1:  s = wk; d = g_wk; break;
            case 2:  s = wv; d = g_wv; break;
            default: s = wp; d = g_wp; break;
        }
    }
    float4 v = s[off];
    __half2 h01 = __floats2half2_rn(v.x, v.y);
    __half2 h23 = __floats2half2_rn(v.z, v.w);
    uint2 u;
    u.x = *(unsigned*)&h01;
    u.y = *(unsigned*)&h23;
    *(uint2*)(d + off * 4) = u;
}

// ---------------------------------------------------------------------------
// FP16 NT GEMM: block tile 128x128, warp tile 32x64 (8 warps, 4x2), BK=64,
// cp.async 2-stage. Per k16 step/warp: 6 LDSM -> 16 MMA.
// ---------------------------------------------------------------------------
#define GBM 128
#define GBN 128
#define GBK 64
#define GPD 72                            // halves per row (144B pitch)
#define A_BYTES (GBM*GPD*2)               // 18432
#define B_BYTES (GBN*GPD*2)               // 18432
#define STG_BYTES (A_BYTES + B_BYTES)     // 36864
#define GEMM_SMEM_BYTES (2*STG_BYTES)     // 73728

__device__ __forceinline__ void gemm_tc(const __half* __restrict__ A,
                                        const __half* __restrict__ W,
                                        float C[2][8][4], int m0, int n0)
{
    extern __shared__ unsigned char smp[];
    const unsigned sbase = smem_u32(smp);

    const int tid  = threadIdx.x;
    const int wid  = tid >> 5;
    const int lane = tid & 31;
    const int wr   = wid >> 1;   // m offset wr*32
    const int wc   = wid & 1;    // n offset wc*64

    const int aRow = lane & 15;
    const int aCol = ((lane >> 4) & 1) << 3;
    const int bRow = (lane & 7) + (((lane >> 4) & 1) << 3);
    const int bCol = ((lane >> 3) & 1) << 3;

    // staging: A and B each 128 rows x 8 chunks = 1024 chunks; 4 per thread
    auto stage = [&](unsigned soff, int k0) {
        #pragma unroll
        for (int i = 0; i < 4; i++) {
            const int c   = tid + i * 256;
            const int row = c >> 3;
            const int c8  = (c & 7) << 3;
            cpa16(sbase + soff + (unsigned)(row * GPD + c8) * 2,
                  A + (size_t)(m0 + row) * NC + k0 + c8);
        }
        #pragma unroll
        for (int i = 0; i < 4; i++) {
            const int c   = tid + i * 256;
            const int row = c >> 3;
            const int c8  = (c & 7) << 3;
            cpa16(sbase + soff + A_BYTES + (unsigned)(row * GPD + c8) * 2,
                  W + (size_t)(n0 + row) * NC + k0 + c8);
        }
    };

    stage(0, 0);
    cp_commit();

    const int NIT = NC / GBK;   // 16
    for (int it = 0; it < NIT; it++) {
        cp_wait<0>();
        __syncthreads();
        if (it + 1 < NIT) {
            stage((unsigned)((it + 1) & 1) * STG_BYTES, (it + 1) * GBK);
            cp_commit();
        }
        const unsigned cs = (unsigned)(it & 1) * STG_BYTES;
        const unsigned aBase = sbase + cs;
        const unsigned bBase = sbase + cs + A_BYTES;

        #pragma unroll
        for (int kk = 0; kk < GBK; kk += 16) {
            unsigned a[2][4], b[8][2];
            #pragma unroll
            for (int mt = 0; mt < 2; mt++)
                ldsm4(a[mt][0], a[mt][1], a[mt][2], a[mt][3],
                      aBase + (unsigned)((wr * 32 + mt * 16 + aRow) * GPD + kk + aCol) * 2);
            #pragma unroll
            for (int p = 0; p < 4; p++)
                ldsm4(b[2*p][0], b[2*p][1], b[2*p+1][0], b[2*p+1][1],
                      bBase + (unsigned)((wc * 64 + p * 16 + bRow) * GPD + kk + bCol) * 2);
            #pragma unroll
            for (int mt = 0; mt < 2; mt++)
                #pragma unroll
                for (int nt = 0; nt < 8; nt++)
                    mma_f16(C[mt][nt], a[mt][0], a[mt][1], a[mt][2], a[mt][3],
                            b[nt][0], b[nt][1]);
        }
    }
}

__global__ __launch_bounds__(256, 2)
void qkv_kernel(const float* __restrict__ bq, const float* __restrict__ bk,
                const float* __restrict__ bv)
{
    const __half* W; const float* bias; __half* Out;
    if (blockIdx.z == 0)      { W = g_wq; bias = bq; Out = g_q; }
    else if (blockIdx.z == 1) { W = g_wk; bias = bk; Out = g_k; }
    else                      { W = g_wv; bias = bv; Out = g_v; }

    const int m0 = blockIdx.y * GBM;
    const int n0 = blockIdx.x * GBN;
    float C[2][8][4] = {};
    gemm_tc(g_x, W, C, m0, n0);

    const int lane = threadIdx.x & 31, wid = threadIdx.x >> 5;
    const int g = lane >> 2, t = lane & 3;
    const int wr = wid >> 1, wc = wid & 1;

    #pragma unroll
    for (int mt = 0; mt < 2; mt++) {
        #pragma unroll
        for (int rr = 0; rr < 2; rr++) {
            const int m = m0 + wr * 32 + mt * 16 + g + rr * 8;
            const int b = m >> 11;
            const int tt = m & (NT - 1);
            #pragma unroll
            for (int nt = 0; nt < 8; nt++) {
                const int n  = n0 + wc * 64 + nt * 8 + 2 * t;
                const int h  = n >> 6;
                const int hd = n & 63;
                __half* op = Out + (((size_t)(b * NH + h)) * NT + tt) * ND + hd;
                __half2 hv = __floats2half2_rn(C[mt][nt][rr * 2 + 0] + bias[n],
                                               C[mt][nt][rr * 2 + 1] + bias[n + 1]);
                *(__half2*)op = hv;
            }
        }
    }
}

__global__ __launch_bounds__(256, 2)
void proj_kernel(const float* __restrict__ bp, float* __restrict__ out)
{
    const int m0 = blockIdx.y * GBM;
    const int n0 = blockIdx.x * GBN;
    float C[2][8][4] = {};
    gemm_tc(g_y, g_wp, C, m0, n0);

    const int lane = threadIdx.x & 31, wid = threadIdx.x >> 5;
    const int g = lane >> 2, t = lane & 3;
    const int wr = wid >> 1, wc = wid & 1;

    #pragma unroll
    for (int mt = 0; mt < 2; mt++) {
        #pragma unroll
        for (int rr = 0; rr < 2; rr++) {
            const int m = m0 + wr * 32 + mt * 16 + g + rr * 8;
            #pragma unroll
            for (int nt = 0; nt < 8; nt++) {
                const int n = n0 + wc * 64 + nt * 8 + 2 * t;
                float2 v;
                v.x = C[mt][nt][rr * 2 + 0] + bp[n];
                v.y = C[mt][nt][rr * 2 + 1] + bp[n + 1];
                *(float2*)(out + (size_t)m * NC + n) = v;
            }
        }
    }
}

// ---------------------------------------------------------------------------
// FP16 flash attention, REGISTER-P: S fragments repack directly into the
// A-fragments of the P*V mma (no smem P buffer at all).
// 256 thr / 8 warps / 128 q-rows per block; K,V staged [key][d] via cp.async.
// ---------------------------------------------------------------------------
#define APDH 72
#define KVB (64*APDH*2)                 // 9216 B per buffer
#define ATT_SMEM_BYTES (4*KVB)          // K0 K1 V0 V1 = 36864

__global__ __launch_bounds__(256)
void attn_kernel()
{
    extern __shared__ unsigned char sma[];
    const unsigned sbase = smem_u32(sma);

    const int tid  = threadIdx.x;
    const int wid  = tid >> 5;
    const int lane = tid & 31;
    const int g    = lane >> 2;
    const int t    = lane & 3;

    const int bh = blockIdx.y;
    const int qb = gridDim.x - 1 - blockIdx.x;   // heavy blocks first
    const int q0 = qb * 128;
    const int rb = wid * 16;

    const int bRow = (lane & 7) + (((lane >> 4) & 1) << 3);
    const int bCol = ((lane >> 3) & 1) << 3;
    const int vRow = lane & 15;
    const int vCol = ((lane >> 4) & 1) << 3;

    // ---- Q fragments from gmem (x0.125 exact in fp16) ----
    unsigned Qf[4][4];
    {
        const __half* qp = g_q + ((size_t)bh * NT + q0 + rb) * ND;
        const __half2 s2 = __floats2half2_rn(0.125f, 0.125f);
        #pragma unroll
        for (int kt = 0; kt < 4; kt++) {
            __half2 v;
            v = __hmul2(*(const __half2*)(qp + (g)     * ND + kt * 16 + 2 * t), s2);
            Qf[kt][0] = *(unsigned*)&v;
            v = __hmul2(*(const __half2*)(qp + (g + 8) * ND + kt * 16 + 2 * t), s2);
            Qf[kt][1] = *(unsigned*)&v;
            v = __hmul2(*(const __half2*)(qp + (g)     * ND + kt * 16 + 2 * t + 8), s2);
            Qf[kt][2] = *(unsigned*)&v;
            v = __hmul2(*(const __half2*)(qp + (g + 8) * ND + kt * 16 + 2 * t + 8), s2);
            Qf[kt][3] = *(unsigned*)&v;
        }
    }

    float Of[8][4];
    #pragma unroll
    for (int nt = 0; nt < 8; nt++)
        #pragma unroll
        for (int j = 0; j < 4; j++) Of[nt][j] = 0.f;
    float mrow[2] = {-1e30f, -1e30f};
    float lrow[2] = {0.f, 0.f};

    const __half* kbase = g_k + (size_t)bh * NT * ND;
    const __half* vbase = g_v + (size_t)bh * NT * ND;

    const int ntiles = 2 * qb + 2;

    auto stage_tile = [&](int tile, int buf) {
        const unsigned kDst = sbase + (unsigned)buf * KVB;
        const unsigned vDst = sbase + (unsigned)(2 + buf) * KVB;
        #pragma unroll
        for (int i = 0; i < 2; i++) {
            const int c   = tid + i * 256;
            const int row = c >> 3;
            const int c8  = (c & 7) << 3;
            const unsigned o = (unsigned)(row * APDH + c8) * 2;
            cpa16(kDst + o, kbase + (size_t)(tile * 64 + row) * ND + c8);
            cpa16(vDst + o, vbase + (size_t)(tile * 64 + row) * ND + c8);
        }
    };

    stage_tile(0, 0);
    cp_commit();

    for (int kt0 = 0; kt0 < ntiles; kt0++) {
        const int cur = kt0 & 1;
        cp_wait<0>();
        __syncthreads();
        if (kt0 + 1 < ntiles) {
            stage_tile(kt0 + 1, cur ^ 1);
            cp_commit();
        }
        const unsigned kBuf = sbase + (unsigned)cur * KVB;
        const unsigned vBuf = sbase + (unsigned)(2 + cur) * KVB;

        const bool active = (kt0 * 64) <= (q0 + rb + 15);
        if (active) {
            // ---- S = Q K^T ----
            float Sf[8][4];
            #pragma unroll
            for (int nt = 0; nt < 8; nt++)
                #pragma unroll
                for (int j = 0; j < 4; j++) Sf[nt][j] = 0.f;

            #pragma unroll
            for (int kt = 0; kt < 4; kt++) {
                unsigned b[8][2];
                #pragma unroll
                for (int p = 0; p < 4; p++)
                    ldsm4(b[2*p][0], b[2*p][1], b[2*p+1][0], b[2*p+1][1],
                          kBuf + (unsigned)((p * 16 + bRow) * APDH + kt * 16 + bCol) * 2);
                #pragma unroll
                for (int nt = 0; nt < 8; nt++)
                    mma_f16(Sf[nt], Qf[kt][0], Qf[kt][1], Qf[kt][2], Qf[kt][3],
                            b[nt][0], b[nt][1]);
            }

            // ---- causal mask (diagonal tiles only) ----
            if (kt0 >= 2 * qb) {
                #pragma unroll
                for (int nt = 0; nt < 8; nt++)
                    #pragma unroll
                    for (int j = 0; j < 4; j++) {
                        const int key = kt0 * 64 + nt * 8 + 2 * t + (j & 1);
                        const int qr  = q0 + rb + g + (j >> 1) * 8;
                        if (key > qr) Sf[nt][j] = -1e30f;
                    }
            }

            // ---- online softmax ----
            #pragma unroll
            for (int r = 0; r < 2; r++) {
                float rm = -1e30f;
                #pragma unroll
                for (int nt = 0; nt < 8; nt++) {
                    rm = fmaxf(rm, Sf[nt][2 * r]);
                    rm = fmaxf(rm, Sf[nt][2 * r + 1]);
                }
                rm = fmaxf(rm, __shfl_xor_sync(0xffffffff, rm, 1));
                rm = fmaxf(rm, __shfl_xor_sync(0xffffffff, rm, 2));
                const float mn   = fmaxf(mrow[r], rm);
                const float corr = __expf(mrow[r] - mn);
                mrow[r] = mn;
                float rs = 0.f;
                #pragma unroll
                for (int nt = 0; nt < 8; nt++) {
                    const float p0 = __expf(Sf[nt][2 * r]     - mn);
                    const float p1 = __expf(Sf[nt][2 * r + 1] - mn);
                    Sf[nt][2 * r] = p0; Sf[nt][2 * r + 1] = p1;
                    rs += p0 + p1;
                }
                rs += __shfl_xor_sync(0xffffffff, rs, 1);
                rs += __shfl_xor_sync(0xffffffff, rs, 2);
                lrow[r] = lrow[r] * corr + rs;
                #pragma unroll
                for (int nt = 0; nt < 8; nt++) {
                    Of[nt][2 * r]     *= corr;
                    Of[nt][2 * r + 1] *= corr;
                }
            }

            // ---- O += P V : P packed straight from S fragments ----
            #pragma unroll
            for (int kt = 0; kt < 4; kt++) {
                __half2 p0 = __floats2half2_rn(Sf[2*kt][0],   Sf[2*kt][1]);
                __half2 p1 = __floats2half2_rn(Sf[2*kt][2],   Sf[2*kt][3]);
                __half2 p2 = __floats2half2_rn(Sf[2*kt+1][0], Sf[2*kt+1][1]);
                __half2 p3 = __floats2half2_rn(Sf[2*kt+1][2], Sf[2*kt+1][3]);
                const unsigned a0 = *(unsigned*)&p0;
                const unsigned a1 = *(unsigned*)&p1;
                const unsigned a2 = *(unsigned*)&p2;
                const unsigned a3 = *(unsigned*)&p3;
                unsigned b[8][2];
                #pragma unroll
                for (int p = 0; p < 4; p++)
                    ldsm4t(b[2*p][0], b[2*p][1], b[2*p+1][0], b[2*p+1][1],
                           vBuf + (unsigned)((kt * 16 + vRow) * APDH + p * 16 + vCol) * 2);
                #pragma unroll
                for (int nt = 0; nt < 8; nt++)
                    mma_f16(Of[nt], a0, a1, a2, a3, b[nt][0], b[nt][1]);
            }
        }
        __syncthreads();
    }

    // ---- epilogue: divide by l, store half for proj ----
    const float inv0 = 1.0f / lrow[0];
    const float inv1 = 1.0f / lrow[1];
    const int b = bh >> 4;
    const int h = bh & 15;
    __half* yp = g_y + ((size_t)(b * NT) + q0 + rb) * NC + h * ND;

    #pragma unroll
    for (int nt = 0; nt < 8; nt++) {
        const int c = nt * 8 + 2 * t;
        __half2 v0 = __floats2half2_rn(Of[nt][0] * inv0, Of[nt][1] * inv0);
        *(__half2*)(yp + (size_t)g * NC + c) = v0;
        __half2 v1 = __floats2half2_rn(Of[nt][2] * inv1, Of[nt][3] * inv1);
        *(__half2*)(yp + (size_t)(g + 8) * NC + c) = v1;
    }
}

// ---------------------------------------------------------------------------
extern "C" void kernel_launch(void* const* d_in, const int* in_sizes, int n_in,
                              void* d_out, int out_size)
{
    const float* x  = (const float*)d_in[0];
    const float* Wk = (const float*)d_in[1];
    const float* bk = (const float*)d_in[2];
    const float* Wq = (const float*)d_in[3];
    const float* bq = (const float*)d_in[4];
    const float* Wv = (const float*)d_in[5];
    const float* bv = (const float*)d_in[6];
    const float* Wp = (const float*)d_in[7];
    const float* bp = (const float*)d_in[8];
    float* out = (float*)d_out;

    static bool attr_done = false;
    if (!attr_done) {
        cudaFuncSetAttribute(qkv_kernel,
                             cudaFuncAttributeMaxDynamicSharedMemorySize, GEMM_SMEM_BYTES);
        cudaFuncSetAttribute(proj_kernel,
                             cudaFuncAttributeMaxDynamicSharedMemorySize, GEMM_SMEM_BYTES);
        cudaFuncSetAttribute(attn_kernel,
                             cudaFuncAttributeMaxDynamicSharedMemorySize, ATT_SMEM_BYTES);
        attr_done = true;
    }

    prep_f16<<<(TOT4 + 255) / 256, 256>>>((const float4*)x,  (const float4*)Wq,
                                          (const float4*)Wk, (const float4*)Wv,
                                          (const float4*)Wp);

    dim3 gq(NC / GBN, MTOT / GBM, 3);
    qkv_kernel<<<gq, 256, GEMM_SMEM_BYTES>>>(bq, bk, bv);

    dim3 ga(NT / 128, NB * NH);
    attn_kernel<<<ga, 256, ATT_SMEM_BYTES>>>();

    dim3 gp(NC / GBN, MTOT / GBM);
    proj_kernel<<<gp, 256, GEMM_SMEM_BYTES>>>(bp, out);
}